// round 14
// baseline (speedup 1.0000x reference)
#include <cuda_runtime.h>
#include <cuda_bf16.h>
#include <cstdint>

// ---------------------------------------------------------------------------
// Problem constants
// ---------------------------------------------------------------------------
#define A_N 64          // batch per set
#define T_N 128         // time steps
#define D_N 128         // feature dim
#define MM  127         // increments per path
#define NTRI 2080       // 64*65/2 upper-triangle pairs
#define NJOBS 8256      // 2080 (XX) + 2080 (YY) + 4096 (XY)
#define NPATH 128       // 64 X paths + 64 Y paths

// Fragment-permuted storage: per path 8 k16-chunks x 16 r8-groups x 32 lanes
// x 2 subs x 4B  = 32KB  (8192 uint32 granules per path)
#define GR_PER_PATH 8192
#define HALF_U32   4096                // uint32 granules per K-half (k16 0-3 / 4-7)

// GEMM kernel smem: 4 fragment K-HALF tiles of 16KB: [AH][AL][BH][BL]
#define TILE_U2   2048                 // uint2 granules per 16KB half-tile
#define M_STRIDE  128
#define M_PER_JOB (128 * 128)          // floats of M' per job
#define SMEM_DYN  (64 * 1024)

// PDE kernel geometry: 1 warp per job, 32 warps per CTA
#define PDE_WARPS_PER_CTA 32
#define PDE_CTAS (NJOBS / PDE_WARPS_PER_CTA)   // 258

// ---------------------------------------------------------------------------
// Scratch (static __device__ arrays: allocation-free per harness rules)
// ---------------------------------------------------------------------------
__device__ __align__(16) unsigned int g_fragH[NPATH * GR_PER_PATH];  // bf16 hi
__device__ __align__(16) unsigned int g_fragL[NPATH * GR_PER_PATH];  // bf16 lo
__device__ __align__(16) float g_M[(size_t)NJOBS * M_PER_JOB];       // M'-1, 541MB
__device__ float g_res[NJOBS];

// ---------------------------------------------------------------------------
// Warp mma: m16n8k16 row.col f32.bf16.bf16.f32  (HMMA, legal at compute_103)
// ---------------------------------------------------------------------------
__device__ __forceinline__ void mma_bf16(float* d, uint2 a0, uint2 a1, uint2 b) {
    asm volatile(
        "mma.sync.aligned.m16n8k16.row.col.f32.bf16.bf16.f32 "
        "{%0,%1,%2,%3}, {%4,%5,%6,%7}, {%8,%9}, {%0,%1,%2,%3};"
        : "+f"(d[0]), "+f"(d[1]), "+f"(d[2]), "+f"(d[3])
        : "r"(a0.x), "r"(a1.x), "r"(a0.y), "r"(a1.y), "r"(b.x), "r"(b.y));
}

// granule-pair index within one K-HALF tile (uint2 units), kk = k16 within half
__device__ __forceinline__ int tidx(int kk, int r8, int lane) {
    return (kk * 16 + r8) * 32 + lane;
}

// job -> (p, q, weight) decode, shared by both kernels
__device__ __forceinline__ void decode_job(int job, int& p, int& q, float& w) {
    w = 1.0f;
    if (job < 2 * NTRI) {
        bool isY = job >= NTRI;
        int t = isY ? job - NTRI : job;
        int a = 0, rl = A_N;
        while (t >= rl) { t -= rl; rl--; a++; }
        int b = a + t;
        int off = isY ? A_N : 0;
        p = a + off;
        q = b + off;
        w = (a == b) ? 1.0f : 2.0f;     // symmetric gram: off-diag twice
    } else {
        int t = job - 2 * NTRI;
        p = (t >> 6);
        q = A_N + (t & 63);
    }
}

// ---------------------------------------------------------------------------
// Prologue: increments dZ = Z[:,1:]-Z[:,:-1] (row 127 zero-padded), split
// into bf16 hi + bf16 lo, stored directly in mma-fragment-permuted layout.
// ---------------------------------------------------------------------------
__global__ void sig_prep_kernel(const float* __restrict__ X,
                                const float* __restrict__ Y) {
    int t = blockIdx.x * blockDim.x + threadIdx.x;
    if (t >= NPATH * GR_PER_PATH) return;
    int path = t >> 13;                 // /8192
    int rem  = t & 8191;
    int k16  = rem >> 10;
    int rem2 = rem & 1023;
    int r8   = rem2 >> 6;
    int rem3 = rem2 & 63;
    int lane = rem3 >> 1;
    int sub  = rem3 & 1;
    int g  = lane >> 2;
    int tc = lane & 3;
    int r  = r8 * 8 + g;
    int k  = k16 * 16 + sub * 8 + tc * 2;

    float d0 = 0.0f, d1 = 0.0f;
    if (r < MM) {
        const float* src = (path < A_N) ? (X + path * T_N * D_N)
                                        : (Y + (path - A_N) * T_N * D_N);
        const float* p0 = src + r * D_N + k;
        d0 = p0[D_N] - p0[0];
        d1 = p0[D_N + 1] - p0[1];
    }
    __nv_bfloat16 h0 = __float2bfloat16(d0);
    __nv_bfloat16 h1 = __float2bfloat16(d1);
    __nv_bfloat16 l0 = __float2bfloat16(d0 - __bfloat162float(h0));
    __nv_bfloat16 l1 = __float2bfloat16(d1 - __bfloat162float(h1));
    unsigned int hp = ((unsigned int)__bfloat16_as_ushort(h1) << 16) |
                       (unsigned int)__bfloat16_as_ushort(h0);
    unsigned int lp = ((unsigned int)__bfloat16_as_ushort(l1) << 16) |
                       (unsigned int)__bfloat16_as_ushort(l0);
    g_fragH[t] = hp;
    g_fragL[t] = lp;
}

// ---------------------------------------------------------------------------
// GEMM kernel: one CTA (256 threads, 8 warps) per job.
//   For each K-half: cooperative 64KB smem stage, then mma.sync bf16
//   3-pass split (hh+hl+lh), 64 fp32 accumulators register-resident.
//   Epilogue: STG (M - 1) straight from accumulators to g_M[job] (no PDE,
//   no smem M, no tail sync -> full 8-warp utilization until CTA exit).
// ---------------------------------------------------------------------------
__global__ __launch_bounds__(256, 2) void sig_gemm_kernel() {
    extern __shared__ float smem[];
    uint2* sAH = (uint2*)smem;
    uint2* sAL = sAH + TILE_U2;
    uint2* sBH = sAL + TILE_U2;
    uint2* sBL = sBH + TILE_U2;

    const int job = blockIdx.x;
    const int tid = threadIdx.x;
    const int lane = tid & 31;
    const int wid = tid >> 5;
    const int wm = wid >> 2;    // 0..1 (m-block within half)
    const int wn = wid & 3;     // 0..3 (n-block)

    int p, q; float w;
    decode_job(job, p, q, w);
    (void)w;

    const int g8 = lane >> 2;
    const int tc = lane & 3;
    float acc[2][2][4][4];              // [half][ms][ns][c]
#pragma unroll
    for (int h = 0; h < 2; h++)
#pragma unroll
        for (int ms = 0; ms < 2; ms++)
#pragma unroll
            for (int ns = 0; ns < 4; ns++)
#pragma unroll
                for (int c = 0; c < 4; c++) acc[h][ms][ns][c] = 0.0f;

#pragma unroll
    for (int kh = 0; kh < 2; kh++) {
        // --- stage this K-half's tiles (each a contiguous 16KB gmem block) ---
        {
            const uint4* gAH = (const uint4*)(g_fragH + p * GR_PER_PATH + kh * HALF_U32);
            const uint4* gAL = (const uint4*)(g_fragL + p * GR_PER_PATH + kh * HALF_U32);
            const uint4* gBH = (const uint4*)(g_fragH + q * GR_PER_PATH + kh * HALF_U32);
            const uint4* gBL = (const uint4*)(g_fragL + q * GR_PER_PATH + kh * HALF_U32);
            uint4* dAH = (uint4*)sAH;
            uint4* dAL = (uint4*)sAL;
            uint4* dBH = (uint4*)sBH;
            uint4* dBL = (uint4*)sBL;
#pragma unroll
            for (int it = 0; it < 4; it++) {
                int i = it * 256 + tid;     // 1024 uint4 per 16KB half-tile
                dAH[i] = gAH[i];
                dAL[i] = gAL[i];
                dBH[i] = gBH[i];
                dBL[i] = gBL[i];
            }
        }
        __syncthreads();

        // --- GEMM over this half's 4 k16 steps ---
#pragma unroll
        for (int h = 0; h < 2; h++) {
            const int r8base = 8 * h + 4 * wm;
#pragma unroll
            for (int kk = 0; kk < 4; kk++) {
                uint2 aH[2][2], aL[2][2];
#pragma unroll
                for (int ms = 0; ms < 2; ms++) {
                    int r8 = r8base + 2 * ms;
                    aH[ms][0] = sAH[tidx(kk, r8, lane)];
                    aH[ms][1] = sAH[tidx(kk, r8 + 1, lane)];
                    aL[ms][0] = sAL[tidx(kk, r8, lane)];
                    aL[ms][1] = sAL[tidx(kk, r8 + 1, lane)];
                }
#pragma unroll
                for (int ns = 0; ns < 4; ns++) {
                    int j8 = 4 * wn + ns;
                    uint2 bH = sBH[tidx(kk, j8, lane)];
                    uint2 bL = sBL[tidx(kk, j8, lane)];
#pragma unroll
                    for (int ms = 0; ms < 2; ms++) {
                        mma_bf16(acc[h][ms][ns], aH[ms][0], aH[ms][1], bH);  // hi*hi
                        mma_bf16(acc[h][ms][ns], aH[ms][0], aH[ms][1], bL);  // hi*lo
                        mma_bf16(acc[h][ms][ns], aL[ms][0], aL[ms][1], bH);  // lo*hi
                    }
                }
            }
        }
        if (kh == 0) __syncthreads();   // reads done before restage
    }

    // --- epilogue: STG (M - 1) straight to gmem ---
    float* gm = g_M + (size_t)job * M_PER_JOB;
#pragma unroll
    for (int h = 0; h < 2; h++)
#pragma unroll
        for (int ms = 0; ms < 2; ms++) {
            int row0 = 64 * h + 32 * wm + 16 * ms + g8;
#pragma unroll
            for (int ns = 0; ns < 4; ns++) {
                int col = 32 * wn + 8 * ns + 2 * tc;
                *(float2*)&gm[row0 * M_STRIDE + col] =
                    make_float2(acc[h][ms][ns][0] - 1.0f, acc[h][ms][ns][1] - 1.0f);
                *(float2*)&gm[(row0 + 8) * M_STRIDE + col] =
                    make_float2(acc[h][ms][ns][2] - 1.0f, acc[h][ms][ns][3] - 1.0f);
            }
        }
}

// ---------------------------------------------------------------------------
// PDE kernel: one WARP per job, 32 warps per CTA (1024 threads), no smem.
//   Register-resident wavefront: lane L owns rows i = 4L+1 .. 4L+4.
//   K[i][j] = K[i][j-1] + K[i-1][j] + K[i-1][j-1] * M'[i-1][j-1]
//   M' read row-sequentially per lane -> L1-line reuse (~31/32 hits),
//   full 228KB L1 (zero smem carveout).  Latency hidden by 64 warps/SM.
// ---------------------------------------------------------------------------
__global__ __launch_bounds__(1024) void sig_pde_kernel() {
    const int lane = threadIdx.x & 31;
    const int wid = threadIdx.x >> 5;
    const int job = blockIdx.x * PDE_WARPS_PER_CTA + wid;

    int p, q; float w;
    decode_job(job, p, q, w);
    (void)p; (void)q;

    const float* __restrict__ gm = g_M + (size_t)job * M_PER_JOB;

    float vp[4], vp2[4];
    int base[4], irow[4];
#pragma unroll
    for (int r = 0; r < 4; r++) {
        vp[r] = 1.0f; vp2[r] = 1.0f;
        int i = 4 * lane + r + 1;
        irow[r] = i;
        base[r] = (i - 1) * M_STRIDE - i - 1;   // gm[base[r] + dg] = M'[i-1][dg-i-1]
    }

    // dg in [2,128]: cells with dg <= i are boundary -> value 1.
#pragma unroll 4
    for (int dg = 2; dg <= 128; dg++) {
        float up  = __shfl_up_sync(0xffffffffu, vp[3], 1);
        float up2 = __shfl_up_sync(0xffffffffu, vp2[3], 1);
        if (lane == 0) { up = 1.0f; up2 = 1.0f; }   // row 0 boundary
        float nv[4];
#pragma unroll
        for (int r = 0; r < 4; r++) {
            float m  = __ldg(&gm[base[r] + dg]);
            float u  = (r == 0) ? up  : vp[r - 1];
            float u2 = (r == 0) ? up2 : vp2[r - 1];
            float comp = fmaf(u2, m, vp[r] + u);
            nv[r] = (dg <= irow[r]) ? 1.0f : comp;
        }
#pragma unroll
        for (int r = 0; r < 4; r++) { vp2[r] = vp[r]; vp[r] = nv[r]; }
    }

    // dg in [129,254]: rows finish when dg-i > 127 (hold value).
#pragma unroll 4
    for (int dg = 129; dg <= 254; dg++) {
        float up  = __shfl_up_sync(0xffffffffu, vp[3], 1);
        float up2 = __shfl_up_sync(0xffffffffu, vp2[3], 1);
        if (lane == 0) { up = 1.0f; up2 = 1.0f; }
        float nv[4];
#pragma unroll
        for (int r = 0; r < 4; r++) {
            float m  = __ldg(&gm[base[r] + dg]);
            float u  = (r == 0) ? up  : vp[r - 1];
            float u2 = (r == 0) ? up2 : vp2[r - 1];
            float comp = fmaf(u2, m, vp[r] + u);
            nv[r] = (dg - irow[r] <= 127) ? comp : vp[r];
        }
#pragma unroll
        for (int r = 0; r < 4; r++) { vp2[r] = vp[r]; vp[r] = nv[r]; }
    }

    // K[127][127] lives on lane 31, r = 2 (i = 127).
    if (lane == 31) g_res[job] = w * vp[2];
}

// ---------------------------------------------------------------------------
// Deterministic reduction: mmd = mean(KXX) + mean(KYY) - 2*mean(KXY)
// ---------------------------------------------------------------------------
__global__ void sig_finalize_kernel(float* __restrict__ out) {
    __shared__ double sh0[256], sh1[256], sh2[256];
    int tid = threadIdx.x;
    double xx = 0.0, yy = 0.0, xy = 0.0;
    for (int idx = tid; idx < NJOBS; idx += 256) {
        double v = (double)g_res[idx];
        if (idx < NTRI) xx += v;
        else if (idx < 2 * NTRI) yy += v;
        else xy += v;
    }
    sh0[tid] = xx; sh1[tid] = yy; sh2[tid] = xy;
    __syncthreads();
    for (int s = 128; s > 0; s >>= 1) {
        if (tid < s) {
            sh0[tid] += sh0[tid + s];
            sh1[tid] += sh1[tid + s];
            sh2[tid] += sh2[tid + s];
        }
        __syncthreads();
    }
    if (tid == 0) {
        double m = sh0[0] / 4096.0 + sh1[0] / 4096.0 - 2.0 * sh2[0] / 4096.0;
        out[0] = (float)m;
    }
}

// ---------------------------------------------------------------------------
extern "C" void kernel_launch(void* const* d_in, const int* in_sizes, int n_in,
                              void* d_out, int out_size) {
    (void)in_sizes; (void)n_in; (void)out_size;
    const float* X = (const float*)d_in[0];
    const float* Y = (const float*)d_in[1];
    float* out = (float*)d_out;

    cudaFuncSetAttribute(sig_gemm_kernel,
                         cudaFuncAttributeMaxDynamicSharedMemorySize, SMEM_DYN);

    const int ngr = NPATH * GR_PER_PATH;
    sig_prep_kernel<<<(ngr + 255) / 256, 256>>>(X, Y);
    sig_gemm_kernel<<<NJOBS, 256, SMEM_DYN>>>();
    sig_pde_kernel<<<PDE_CTAS, 1024>>>();
    sig_finalize_kernel<<<1, 256>>>(out);
}